// round 11
// baseline (speedup 1.0000x reference)
#include <cuda_runtime.h>
#include <cuda_bf16.h>
#include <cstdint>

// AttentionLayer: B=2048, F=128, E=64, H=4, A=64
//   out[b,f,h*64+a] = relu( softmax(q k^T) v + (feature @ res_w)[:, h*64:] )
//
// mma.sync bf16 hi/lo 3-term emulated fp32 on all five GEMMs.
// Register-resident dataflow: f, q, P, res live in registers; only B operands
// (weights, k, v) go through SMEM. B-fragment ldsm double-buffered in regs.
// 1 CTA per (b,h), 256 threads, warp w owns rows [16w,16w+16).

#define B_ 2048
#define F_ 128
#define E_ 64
#define H_ 4
#define A_ 64

// ---------------- smem layout (bytes); bf16 tiles, row stride 144 B --------
#define SM_WQH 0        // weight tiles [64x64] row-major [e][a]
#define SM_WQL 9216
#define SM_WKH 18432
#define SM_WKL 27648
#define SM_WVH 36864
#define SM_WVL 46080
#define SM_RH  55296    // res_w slice [64x64]
#define SM_RL  64512
#define SM_KH  73728    // k [128x64] row-major [g][a]
#define SM_KL  92160
#define SM_VH  110592   // v [128x64] row-major [g][a]
#define SM_VL  129024
#define SMEM_BYTES 147456

// ---------------- PTX helpers ----------------------------------------------
__device__ __forceinline__ uint32_t smem_u32(const void* p) {
    uint32_t a;
    asm("{ .reg .u64 t; cvta.to.shared.u64 t, %1; cvt.u32.u64 %0, t; }"
        : "=r"(a) : "l"(p));
    return a;
}
__device__ __forceinline__ void ldsm4(uint32_t addr, uint32_t r[4]) {
    asm volatile("ldmatrix.sync.aligned.m8n8.x4.shared.b16 {%0,%1,%2,%3}, [%4];"
                 : "=r"(r[0]), "=r"(r[1]), "=r"(r[2]), "=r"(r[3]) : "r"(addr));
}
__device__ __forceinline__ void ldsm4t(uint32_t addr, uint32_t r[4]) {
    asm volatile("ldmatrix.sync.aligned.m8n8.x4.trans.shared.b16 {%0,%1,%2,%3}, [%4];"
                 : "=r"(r[0]), "=r"(r[1]), "=r"(r[2]), "=r"(r[3]) : "r"(addr));
}
__device__ __forceinline__ void mma16816(float d[4], const uint32_t a[4],
                                         uint32_t b0, uint32_t b1) {
    asm volatile(
        "mma.sync.aligned.m16n8k16.row.col.f32.bf16.bf16.f32 "
        "{%0,%1,%2,%3}, {%4,%5,%6,%7}, {%8,%9}, {%0,%1,%2,%3};"
        : "+f"(d[0]), "+f"(d[1]), "+f"(d[2]), "+f"(d[3])
        : "r"(a[0]), "r"(a[1]), "r"(a[2]), "r"(a[3]), "r"(b0), "r"(b1));
}
// 3-term hi/lo MMA pair for two adjacent 8-col accumulators
__device__ __forceinline__ void mma3(float dA[4], float dB[4],
                                     const uint32_t ah[4], const uint32_t al[4],
                                     const uint32_t bh[4], const uint32_t bl[4]) {
    mma16816(dA, ah, bh[0], bh[1]);
    mma16816(dB, ah, bh[2], bh[3]);
    mma16816(dA, ah, bl[0], bl[1]);
    mma16816(dB, ah, bl[2], bl[3]);
    mma16816(dA, al, bh[0], bh[1]);
    mma16816(dB, al, bh[2], bh[3]);
}

// packed conversions: cvt.rn.bf16x2.f32 packs (hi_half=x, lo_half=y)
__device__ __forceinline__ uint32_t cvt_bf2(float lo_val, float hi_val) {
    uint32_t r;
    asm("cvt.rn.bf16x2.f32 %0, %1, %2;" : "=r"(r) : "f"(hi_val), "f"(lo_val));
    return r;
}
// hi/lo split of (a,b): returns packed hi pair (a low half), writes packed lo.
__device__ __forceinline__ uint32_t pack_hilo(float a, float b, uint32_t& lo) {
    uint32_t hi = cvt_bf2(a, b);
    float ha = __uint_as_float(hi << 16);            // bf16 -> f32 exact
    float hb = __uint_as_float(hi & 0xFFFF0000u);
    lo = cvt_bf2(a - ha, b - hb);
    return hi;
}

__global__ __launch_bounds__(256, 1)
void attn_mma_kernel(const float* __restrict__ feature,
                     const float* __restrict__ Qw,
                     const float* __restrict__ Kw,
                     const float* __restrict__ Vw,
                     const float* __restrict__ res_w,
                     float* __restrict__ out) {
    extern __shared__ char smem[];
    const uint32_t sb = smem_u32(smem);
    const int t = threadIdx.x;
    const int w = t >> 5, l = t & 31;
    const int grp = l >> 2, qt = l & 3;      // C/A-fragment coords
    const int lr = l & 7, lm = l >> 3;       // ldmatrix lane coords
    const int b = blockIdx.x >> 2, h = blockIdx.x & 3;
    const int r0 = w * 16;                   // warp's output row base

    // ======== Phase 0a: f -> register A-fragments (hi/lo), loaded once =====
    uint32_t fh[4][4], fl[4][4];
    {
        const float* fb = feature + (size_t)b * (F_ * E_) + (size_t)r0 * E_;
        #pragma unroll
        for (int ks = 0; ks < 4; ks++) {
            float2 v0 = *(const float2*)(fb + grp * 64 + ks * 16 + qt * 2);
            float2 v1 = *(const float2*)(fb + (grp + 8) * 64 + ks * 16 + qt * 2);
            float2 v2 = *(const float2*)(fb + grp * 64 + ks * 16 + 8 + qt * 2);
            float2 v3 = *(const float2*)(fb + (grp + 8) * 64 + ks * 16 + 8 + qt * 2);
            fh[ks][0] = pack_hilo(v0.x, v0.y, fl[ks][0]);
            fh[ks][1] = pack_hilo(v1.x, v1.y, fl[ks][1]);
            fh[ks][2] = pack_hilo(v2.x, v2.y, fl[ks][2]);
            fh[ks][3] = pack_hilo(v3.x, v3.y, fl[ks][3]);
        }
    }

    // ======== Phase 0b: weights -> smem bf16 hi/lo (cooperative) ===========
    {
        const float* srcs[4] = {Qw + h * (E_ * A_), Kw + h * (E_ * A_),
                                Vw + h * (E_ * A_), res_w + h * A_};
        const int strd[4] = {A_, A_, A_, H_ * A_};
        const int dsth[4] = {SM_WQH, SM_WKH, SM_WVH, SM_RH};
        const int dstl[4] = {SM_WQL, SM_WKL, SM_WVL, SM_RL};
        #pragma unroll
        for (int p = 0; p < 4; p++) {
            const float* s = srcs[p];
            const int st = strd[p];
            #pragma unroll
            for (int it = 0; it < 4; it++) {
                int i = t + it * 256;
                int e = i >> 4, c4 = (i & 15) << 2;
                float4 v = *(const float4*)(s + e * st + c4);
                uint32_t lo0, lo1;
                uint32_t h0 = pack_hilo(v.x, v.y, lo0);
                uint32_t h1 = pack_hilo(v.z, v.w, lo1);
                uint32_t off = (uint32_t)(e * 144 + (c4 << 1));
                *(uint2*)(smem + dsth[p] + off) = make_uint2(h0, h1);
                *(uint2*)(smem + dstl[p] + off) = make_uint2(lo0, lo1);
            }
        }
    }
    __syncthreads();

    // GEMM with register A-frags; B [K=64][N=64] row-major (.trans loads),
    // B-fragments double-buffered in registers to hide LDSM latency.
    auto gemmA = [&](const uint32_t ah[4][4], const uint32_t al[4][4],
                     uint32_t bh_off, uint32_t bl_off, float acc[8][4]) {
        const uint32_t base_h = sb + bh_off, base_l = sb + bl_off;
        auto baddr = [&](int ks, int p) {
            return (uint32_t)(((ks << 4) + lr + ((lm & 1) << 3)) * 144 +
                              (p << 5) + ((lm >> 1) << 4));
        };
        uint32_t bh[2][4], bl[2][4];
        {
            uint32_t rel = baddr(0, 0);
            ldsm4t(base_h + rel, bh[0]);
            ldsm4t(base_l + rel, bl[0]);
        }
        #pragma unroll
        for (int it = 0; it < 16; it++) {
            const int ks = it >> 2, p = it & 3, cur = it & 1;
            if (it < 15) {
                uint32_t rel = baddr((it + 1) >> 2, (it + 1) & 3);
                ldsm4t(base_h + rel, bh[cur ^ 1]);
                ldsm4t(base_l + rel, bl[cur ^ 1]);
            }
            mma3(acc[2 * p], acc[2 * p + 1], ah[ks], al[ks], bh[cur], bl[cur]);
        }
    };
    // C-frag -> A-frag conversion (hi/lo split), 4 k-chunks from 8 col-tiles
    auto to_frag4 = [&](const float acc[8][4], uint32_t oh[4][4], uint32_t ol[4][4]) {
        #pragma unroll
        for (int ks = 0; ks < 4; ks++) {
            oh[ks][0] = pack_hilo(acc[2 * ks][0],     acc[2 * ks][1],     ol[ks][0]);
            oh[ks][1] = pack_hilo(acc[2 * ks][2],     acc[2 * ks][3],     ol[ks][1]);
            oh[ks][2] = pack_hilo(acc[2 * ks + 1][0], acc[2 * ks + 1][1], ol[ks][2]);
            oh[ks][3] = pack_hilo(acc[2 * ks + 1][2], acc[2 * ks + 1][3], ol[ks][3]);
        }
    };
    // store C tile (16 rows x 64 cols) to smem as bf16 hi/lo, stride 144
    auto store_hilo = [&](const float acc[8][4], int oh, int ol) {
        #pragma unroll
        for (int i = 0; i < 8; i++) {
            int cbyte = (((i << 3) + (qt << 1)) << 1);
            uint32_t lo;
            uint32_t hi = pack_hilo(acc[i][0], acc[i][1], lo);
            *(uint32_t*)(smem + oh + (r0 + grp) * 144 + cbyte) = hi;
            *(uint32_t*)(smem + ol + (r0 + grp) * 144 + cbyte) = lo;
            hi = pack_hilo(acc[i][2], acc[i][3], lo);
            *(uint32_t*)(smem + oh + (r0 + grp + 8) * 144 + cbyte) = hi;
            *(uint32_t*)(smem + ol + (r0 + grp + 8) * 144 + cbyte) = lo;
        }
    };

    // ================= Phase 1: projections + res ==========================
    uint32_t qh[4][4], ql[4][4];
    {
        float acc[8][4] = {};
        gemmA(fh, fl, SM_WQH, SM_WQL, acc);
        to_frag4(acc, qh, ql);               // q stays in registers
    }
    {
        float acc[8][4] = {};
        gemmA(fh, fl, SM_WKH, SM_WKL, acc);
        store_hilo(acc, SM_KH, SM_KL);       // k needed by all warps -> smem
    }
    {
        float acc[8][4] = {};
        gemmA(fh, fl, SM_WVH, SM_WVL, acc);
        store_hilo(acc, SM_VH, SM_VL);       // v needed by all warps -> smem
    }
    // res GEMM now (fh/fl die here; racc carried to the epilogue)
    float racc[8][4] = {};
    gemmA(fh, fl, SM_RH, SM_RL, racc);
    __syncthreads();

    // ================= Phase 2: S = q k^T (16 x 128 per warp) ==============
    float sacc[16][4] = {};
    {
        const uint32_t base_h = sb + SM_KH, base_l = sb + SM_KL;
        auto baddr = [&](int ks, int p) {
            return (uint32_t)(((p << 4) + lr + ((lm >> 1) << 3)) * 144 +
                              (ks << 5) + ((lm & 1) << 4));
        };
        uint32_t bh[2][4], bl[2][4];
        {
            uint32_t rel = baddr(0, 0);
            ldsm4(base_h + rel, bh[0]);
            ldsm4(base_l + rel, bl[0]);
        }
        #pragma unroll
        for (int it = 0; it < 32; it++) {
            const int ks = it >> 3, p = it & 7, cur = it & 1;
            if (it < 31) {
                uint32_t rel = baddr((it + 1) >> 3, (it + 1) & 7);
                ldsm4(base_h + rel, bh[cur ^ 1]);
                ldsm4(base_l + rel, bl[cur ^ 1]);
            }
            mma3(sacc[2 * p], sacc[2 * p + 1], qh[ks], ql[ks], bh[cur], bl[cur]);
        }
    }

    // ================= Phase 3: softmax in registers =======================
    float invA, invB;
    {
        float mA = -3.402823466e38f, mB = -3.402823466e38f;
        #pragma unroll
        for (int i = 0; i < 16; i++) {
            mA = fmaxf(mA, fmaxf(sacc[i][0], sacc[i][1]));
            mB = fmaxf(mB, fmaxf(sacc[i][2], sacc[i][3]));
        }
        mA = fmaxf(mA, __shfl_xor_sync(0xFFFFFFFFu, mA, 1));
        mA = fmaxf(mA, __shfl_xor_sync(0xFFFFFFFFu, mA, 2));
        mB = fmaxf(mB, __shfl_xor_sync(0xFFFFFFFFu, mB, 1));
        mB = fmaxf(mB, __shfl_xor_sync(0xFFFFFFFFu, mB, 2));
        float sA = 0.f, sB = 0.f;
        #pragma unroll
        for (int i = 0; i < 16; i++) {
            sacc[i][0] = __expf(sacc[i][0] - mA);
            sacc[i][1] = __expf(sacc[i][1] - mA);
            sacc[i][2] = __expf(sacc[i][2] - mB);
            sacc[i][3] = __expf(sacc[i][3] - mB);
            sA += sacc[i][0] + sacc[i][1];
            sB += sacc[i][2] + sacc[i][3];
        }
        sA += __shfl_xor_sync(0xFFFFFFFFu, sA, 1);
        sA += __shfl_xor_sync(0xFFFFFFFFu, sA, 2);
        sB += __shfl_xor_sync(0xFFFFFFFFu, sB, 1);
        sB += __shfl_xor_sync(0xFFFFFFFFu, sB, 2);
        invA = 1.0f / sA;
        invB = 1.0f / sB;
    }

    // P (unnormalized) -> register A-fragments, 8 k-chunks
    uint32_t ph[8][4], pl[8][4];
    #pragma unroll
    for (int ks = 0; ks < 8; ks++) {
        ph[ks][0] = pack_hilo(sacc[2 * ks][0],     sacc[2 * ks][1],     pl[ks][0]);
        ph[ks][1] = pack_hilo(sacc[2 * ks][2],     sacc[2 * ks][3],     pl[ks][1]);
        ph[ks][2] = pack_hilo(sacc[2 * ks + 1][0], sacc[2 * ks + 1][1], pl[ks][2]);
        ph[ks][3] = pack_hilo(sacc[2 * ks + 1][2], sacc[2 * ks + 1][3], pl[ks][3]);
    }

    // ================= Phase 4: em = P @ v  (K=128) ========================
    float eacc[8][4] = {};
    {
        const uint32_t base_h = sb + SM_VH, base_l = sb + SM_VL;
        auto baddr = [&](int ks, int p) {
            return (uint32_t)(((ks << 4) + lr + ((lm & 1) << 3)) * 144 +
                              (p << 5) + ((lm >> 1) << 4));
        };
        uint32_t bh[2][4], bl[2][4];
        {
            uint32_t rel = baddr(0, 0);
            ldsm4t(base_h + rel, bh[0]);
            ldsm4t(base_l + rel, bl[0]);
        }
        #pragma unroll
        for (int it = 0; it < 32; it++) {
            const int ks = it >> 2, p = it & 3, cur = it & 1;
            if (it < 31) {
                uint32_t rel = baddr((it + 1) >> 2, (it + 1) & 3);
                ldsm4t(base_h + rel, bh[cur ^ 1]);
                ldsm4t(base_l + rel, bl[cur ^ 1]);
            }
            mma3(eacc[2 * p], eacc[2 * p + 1], ph[ks], pl[ks], bh[cur], bl[cur]);
        }
    }

    // ================= Phase 5: epilogue relu(em/sum + res) ================
    {
        #pragma unroll
        for (int i = 0; i < 8; i++) {
            int c = h * A_ + (i << 3) + (qt << 1);
            float2 o;
            o.x = fmaxf(fmaf(eacc[i][0], invA, racc[i][0]), 0.f);
            o.y = fmaxf(fmaf(eacc[i][1], invA, racc[i][1]), 0.f);
            *(float2*)(out + ((size_t)(b * F_) + r0 + grp) * (H_ * A_) + c) = o;
            o.x = fmaxf(fmaf(eacc[i][2], invB, racc[i][2]), 0.f);
            o.y = fmaxf(fmaf(eacc[i][3], invB, racc[i][3]), 0.f);
            *(float2*)(out + ((size_t)(b * F_) + r0 + grp + 8) * (H_ * A_) + c) = o;
        }
    }
}

extern "C" void kernel_launch(void* const* d_in, const int* in_sizes, int n_in,
                              void* d_out, int out_size) {
    const float* feature = (const float*)d_in[0];
    const float* Qw      = (const float*)d_in[1];
    const float* Kw      = (const float*)d_in[2];
    const float* Vw      = (const float*)d_in[3];
    const float* res_w   = (const float*)d_in[4];
    float* out = (float*)d_out;

    cudaFuncSetAttribute(attn_mma_kernel,
                         cudaFuncAttributeMaxDynamicSharedMemorySize, SMEM_BYTES);
    attn_mma_kernel<<<B_ * H_, 256, SMEM_BYTES>>>(feature, Qw, Kw, Vw, res_w, out);
}

// round 12
// speedup vs baseline: 1.5560x; 1.5560x over previous
#include <cuda_runtime.h>
#include <cuda_bf16.h>
#include <cstdint>

// AttentionLayer: B=2048, F=128, E=64, H=4, A=64
//   out[b,f,h*64+a] = relu( softmax(q k^T) v + (feature @ res_w)[:, h*64:] )
//
// mma.sync bf16 hi/lo 3-term emulated fp32 on all five GEMMs.
// Register-resident dataflow: f, q, P live in registers as A-fragments;
// only B operands (weights, k, v) go through SMEM.
// 1 CTA per (b,h), 256 threads, warp w owns rows [16w,16w+16).
// R12: R10 structure (known-good) + packed bf16x2 conversions + non-volatile
// MMA asm (scheduler freedom) — both register-neutral.

#define B_ 2048
#define F_ 128
#define E_ 64
#define H_ 4
#define A_ 64

// ---------------- smem layout (bytes); bf16 tiles, row stride 144 B --------
#define SM_WQH 0        // weight tiles [64x64] row-major [e][a]
#define SM_WQL 9216
#define SM_WKH 18432
#define SM_WKL 27648
#define SM_WVH 36864
#define SM_WVL 46080
#define SM_RH  55296    // res_w slice [64x64]
#define SM_RL  64512
#define SM_KH  73728    // k [128x64] row-major [g][a]
#define SM_KL  92160
#define SM_VH  110592   // v [128x64] row-major [g][a]
#define SM_VL  129024
#define SMEM_BYTES 147456

// ---------------- PTX helpers ----------------------------------------------
__device__ __forceinline__ uint32_t smem_u32(const void* p) {
    uint32_t a;
    asm("{ .reg .u64 t; cvta.to.shared.u64 t, %1; cvt.u32.u64 %0, t; }"
        : "=r"(a) : "l"(p));
    return a;
}
__device__ __forceinline__ void ldsm4(uint32_t addr, uint32_t r[4]) {
    asm volatile("ldmatrix.sync.aligned.m8n8.x4.shared.b16 {%0,%1,%2,%3}, [%4];"
                 : "=r"(r[0]), "=r"(r[1]), "=r"(r[2]), "=r"(r[3]) : "r"(addr));
}
__device__ __forceinline__ void ldsm4t(uint32_t addr, uint32_t r[4]) {
    asm volatile("ldmatrix.sync.aligned.m8n8.x4.trans.shared.b16 {%0,%1,%2,%3}, [%4];"
                 : "=r"(r[0]), "=r"(r[1]), "=r"(r[2]), "=r"(r[3]) : "r"(addr));
}
// non-volatile: output-register dataflow fully expresses the dependencies,
// so ptxas may schedule MMAs into ldsm latency windows.
__device__ __forceinline__ void mma16816(float d[4], const uint32_t a[4],
                                         uint32_t b0, uint32_t b1) {
    asm("mma.sync.aligned.m16n8k16.row.col.f32.bf16.bf16.f32 "
        "{%0,%1,%2,%3}, {%4,%5,%6,%7}, {%8,%9}, {%0,%1,%2,%3};"
        : "+f"(d[0]), "+f"(d[1]), "+f"(d[2]), "+f"(d[3])
        : "r"(a[0]), "r"(a[1]), "r"(a[2]), "r"(a[3]), "r"(b0), "r"(b1));
}
// 3-term hi/lo MMA pair for two adjacent 8-col accumulators
__device__ __forceinline__ void mma3(float dA[4], float dB[4],
                                     const uint32_t ah[4], const uint32_t al[4],
                                     const uint32_t bh[4], const uint32_t bl[4]) {
    mma16816(dA, ah, bh[0], bh[1]);
    mma16816(dB, ah, bh[2], bh[3]);
    mma16816(dA, ah, bl[0], bl[1]);
    mma16816(dB, ah, bl[2], bl[3]);
    mma16816(dA, al, bh[0], bh[1]);
    mma16816(dB, al, bh[2], bh[3]);
}

// packed conversion: cvt.rn.bf16x2.f32 %0, hi, lo  (first operand -> high half)
__device__ __forceinline__ uint32_t cvt_bf2(float lo_val, float hi_val) {
    uint32_t r;
    asm("cvt.rn.bf16x2.f32 %0, %1, %2;" : "=r"(r) : "f"(hi_val), "f"(lo_val));
    return r;
}
// hi/lo split of (a,b): returns packed hi pair (a in low half), writes packed lo.
// Numerically identical to per-element __float2bfloat16_rn (verified R11).
__device__ __forceinline__ uint32_t pack_hilo(float a, float b, uint32_t& lo) {
    uint32_t hi = cvt_bf2(a, b);
    float ha = __uint_as_float(hi << 16);            // bf16 -> f32 exact
    float hb = __uint_as_float(hi & 0xFFFF0000u);
    lo = cvt_bf2(a - ha, b - hb);
    return hi;
}

__global__ __launch_bounds__(256, 1)
void attn_mma_kernel(const float* __restrict__ feature,
                     const float* __restrict__ Qw,
                     const float* __restrict__ Kw,
                     const float* __restrict__ Vw,
                     const float* __restrict__ res_w,
                     float* __restrict__ out) {
    extern __shared__ char smem[];
    const uint32_t sb = smem_u32(smem);
    const int t = threadIdx.x;
    const int w = t >> 5, l = t & 31;
    const int grp = l >> 2, qt = l & 3;      // C/A-fragment coords
    const int lr = l & 7, lm = l >> 3;       // ldmatrix lane coords
    const int b = blockIdx.x >> 2, h = blockIdx.x & 3;
    const int r0 = w * 16;                   // warp's output row base

    // ======== Phase 0a: f -> register A-fragments (hi/lo), loaded once =====
    uint32_t fh[4][4], fl[4][4];
    {
        const float* fb = feature + (size_t)b * (F_ * E_) + (size_t)r0 * E_;
        #pragma unroll
        for (int ks = 0; ks < 4; ks++) {
            float2 v0 = *(const float2*)(fb + grp * 64 + ks * 16 + qt * 2);
            float2 v1 = *(const float2*)(fb + (grp + 8) * 64 + ks * 16 + qt * 2);
            float2 v2 = *(const float2*)(fb + grp * 64 + ks * 16 + 8 + qt * 2);
            float2 v3 = *(const float2*)(fb + (grp + 8) * 64 + ks * 16 + 8 + qt * 2);
            fh[ks][0] = pack_hilo(v0.x, v0.y, fl[ks][0]);
            fh[ks][1] = pack_hilo(v1.x, v1.y, fl[ks][1]);
            fh[ks][2] = pack_hilo(v2.x, v2.y, fl[ks][2]);
            fh[ks][3] = pack_hilo(v3.x, v3.y, fl[ks][3]);
        }
    }

    // ======== Phase 0b: weights -> smem bf16 hi/lo (cooperative) ===========
    {
        const float* srcs[4] = {Qw + h * (E_ * A_), Kw + h * (E_ * A_),
                                Vw + h * (E_ * A_), res_w + h * A_};
        const int strd[4] = {A_, A_, A_, H_ * A_};
        const int dsth[4] = {SM_WQH, SM_WKH, SM_WVH, SM_RH};
        const int dstl[4] = {SM_WQL, SM_WKL, SM_WVL, SM_RL};
        #pragma unroll
        for (int p = 0; p < 4; p++) {
            const float* s = srcs[p];
            const int st = strd[p];
            #pragma unroll
            for (int it = 0; it < 4; it++) {
                int i = t + it * 256;
                int e = i >> 4, c4 = (i & 15) << 2;
                float4 v = *(const float4*)(s + e * st + c4);
                uint32_t lo0, lo1;
                uint32_t h0 = pack_hilo(v.x, v.y, lo0);
                uint32_t h1 = pack_hilo(v.z, v.w, lo1);
                uint32_t off = (uint32_t)(e * 144 + (c4 << 1));
                *(uint2*)(smem + dsth[p] + off) = make_uint2(h0, h1);
                *(uint2*)(smem + dstl[p] + off) = make_uint2(lo0, lo1);
            }
        }
    }
    __syncthreads();

    // GEMM with register A-frags (4 k-chunks), B from smem [K=64][N=64] (.trans)
    auto gemmA = [&](const uint32_t ah[4][4], const uint32_t al[4][4],
                     uint32_t bh_off, uint32_t bl_off, float acc[8][4]) {
        #pragma unroll
        for (int ks = 0; ks < 4; ks++) {
            #pragma unroll
            for (int p = 0; p < 4; p++) {
                uint32_t b_rel = (uint32_t)(((ks << 4) + lr + ((lm & 1) << 3)) * 144 +
                                            (p << 5) + ((lm >> 1) << 4));
                uint32_t bh[4], bl[4];
                ldsm4t(sb + bh_off + b_rel, bh);
                ldsm4t(sb + bl_off + b_rel, bl);
                mma3(acc[2 * p], acc[2 * p + 1], ah[ks], al[ks], bh, bl);
            }
        }
    };
    // C-frag -> A-frag conversion (hi/lo split), 4 k-chunks from 8 col-tiles
    auto to_frag4 = [&](const float acc[8][4], uint32_t oh[4][4], uint32_t ol[4][4]) {
        #pragma unroll
        for (int ks = 0; ks < 4; ks++) {
            oh[ks][0] = pack_hilo(acc[2 * ks][0],     acc[2 * ks][1],     ol[ks][0]);
            oh[ks][1] = pack_hilo(acc[2 * ks][2],     acc[2 * ks][3],     ol[ks][1]);
            oh[ks][2] = pack_hilo(acc[2 * ks + 1][0], acc[2 * ks + 1][1], ol[ks][2]);
            oh[ks][3] = pack_hilo(acc[2 * ks + 1][2], acc[2 * ks + 1][3], ol[ks][3]);
        }
    };
    // store C tile (16 rows x 64 cols) to smem as bf16 hi/lo, stride 144
    auto store_hilo = [&](const float acc[8][4], int oh, int ol) {
        #pragma unroll
        for (int i = 0; i < 8; i++) {
            int cbyte = (((i << 3) + (qt << 1)) << 1);
            uint32_t lo;
            uint32_t hi = pack_hilo(acc[i][0], acc[i][1], lo);
            *(uint32_t*)(smem + oh + (r0 + grp) * 144 + cbyte) = hi;
            *(uint32_t*)(smem + ol + (r0 + grp) * 144 + cbyte) = lo;
            hi = pack_hilo(acc[i][2], acc[i][3], lo);
            *(uint32_t*)(smem + oh + (r0 + grp + 8) * 144 + cbyte) = hi;
            *(uint32_t*)(smem + ol + (r0 + grp + 8) * 144 + cbyte) = lo;
        }
    };

    // ================= Phase 1: projections ================================
    uint32_t qh[4][4], ql[4][4];
    {
        float acc[8][4] = {};
        gemmA(fh, fl, SM_WQH, SM_WQL, acc);
        to_frag4(acc, qh, ql);               // q stays in registers
    }
    {
        float acc[8][4] = {};
        gemmA(fh, fl, SM_WKH, SM_WKL, acc);
        store_hilo(acc, SM_KH, SM_KL);       // k needed by all warps -> smem
    }
    {
        float acc[8][4] = {};
        gemmA(fh, fl, SM_WVH, SM_WVL, acc);
        store_hilo(acc, SM_VH, SM_VL);       // v needed by all warps -> smem
    }
    __syncthreads();

    // ================= Phase 2: S = q k^T (16 x 128 per warp) ==============
    float sacc[16][4] = {};
    #pragma unroll
    for (int ks = 0; ks < 4; ks++) {
        #pragma unroll
        for (int p = 0; p < 8; p++) {
            uint32_t b_rel = (uint32_t)(((p << 4) + lr + ((lm >> 1) << 3)) * 144 +
                                        (ks << 5) + ((lm & 1) << 4));
            uint32_t bh[4], bl[4];
            ldsm4(sb + SM_KH + b_rel, bh);
            ldsm4(sb + SM_KL + b_rel, bl);
            mma3(sacc[2 * p], sacc[2 * p + 1], qh[ks], ql[ks], bh, bl);
        }
    }

    // ================= Phase 3: softmax in registers =======================
    float invA, invB;
    {
        float mA = -3.402823466e38f, mB = -3.402823466e38f;
        #pragma unroll
        for (int i = 0; i < 16; i++) {
            mA = fmaxf(mA, fmaxf(sacc[i][0], sacc[i][1]));
            mB = fmaxf(mB, fmaxf(sacc[i][2], sacc[i][3]));
        }
        mA = fmaxf(mA, __shfl_xor_sync(0xFFFFFFFFu, mA, 1));
        mA = fmaxf(mA, __shfl_xor_sync(0xFFFFFFFFu, mA, 2));
        mB = fmaxf(mB, __shfl_xor_sync(0xFFFFFFFFu, mB, 1));
        mB = fmaxf(mB, __shfl_xor_sync(0xFFFFFFFFu, mB, 2));
        float sA = 0.f, sB = 0.f;
        #pragma unroll
        for (int i = 0; i < 16; i++) {
            sacc[i][0] = __expf(sacc[i][0] - mA);
            sacc[i][1] = __expf(sacc[i][1] - mA);
            sacc[i][2] = __expf(sacc[i][2] - mB);
            sacc[i][3] = __expf(sacc[i][3] - mB);
            sA += sacc[i][0] + sacc[i][1];
            sB += sacc[i][2] + sacc[i][3];
        }
        sA += __shfl_xor_sync(0xFFFFFFFFu, sA, 1);
        sA += __shfl_xor_sync(0xFFFFFFFFu, sA, 2);
        sB += __shfl_xor_sync(0xFFFFFFFFu, sB, 1);
        sB += __shfl_xor_sync(0xFFFFFFFFu, sB, 2);
        invA = 1.0f / sA;
        invB = 1.0f / sB;
    }

    // P (unnormalized) -> register A-fragments, 8 k-chunks
    uint32_t ph[8][4], pl[8][4];
    #pragma unroll
    for (int ks = 0; ks < 8; ks++) {
        ph[ks][0] = pack_hilo(sacc[2 * ks][0],     sacc[2 * ks][1],     pl[ks][0]);
        ph[ks][1] = pack_hilo(sacc[2 * ks][2],     sacc[2 * ks][3],     pl[ks][1]);
        ph[ks][2] = pack_hilo(sacc[2 * ks + 1][0], sacc[2 * ks + 1][1], pl[ks][2]);
        ph[ks][3] = pack_hilo(sacc[2 * ks + 1][2], sacc[2 * ks + 1][3], pl[ks][3]);
    }

    // ================= Phase 4: em = P @ v  (K=128) ========================
    float eacc[8][4] = {};
    #pragma unroll
    for (int ks = 0; ks < 8; ks++) {
        #pragma unroll
        for (int p = 0; p < 4; p++) {
            uint32_t b_rel = (uint32_t)(((ks << 4) + lr + ((lm & 1) << 3)) * 144 +
                                        (p << 5) + ((lm >> 1) << 4));
            uint32_t bh[4], bl[4];
            ldsm4t(sb + SM_VH + b_rel, bh);
            ldsm4t(sb + SM_VL + b_rel, bl);
            mma3(eacc[2 * p], eacc[2 * p + 1], ph[ks], pl[ks], bh, bl);
        }
    }

    // ================= Phase 5: res = f @ res_w slice ======================
    float racc[8][4] = {};
    gemmA(fh, fl, SM_RH, SM_RL, racc);

    // ================= Phase 6: epilogue relu(em/sum + res) ================
    {
        #pragma unroll
        for (int i = 0; i < 8; i++) {
            int c = h * A_ + (i << 3) + (qt << 1);
            float2 o;
            o.x = fmaxf(fmaf(eacc[i][0], invA, racc[i][0]), 0.f);
            o.y = fmaxf(fmaf(eacc[i][1], invA, racc[i][1]), 0.f);
            *(float2*)(out + ((size_t)(b * F_) + r0 + grp) * (H_ * A_) + c) = o;
            o.x = fmaxf(fmaf(eacc[i][2], invB, racc[i][2]), 0.f);
            o.y = fmaxf(fmaf(eacc[i][3], invB, racc[i][3]), 0.f);
            *(float2*)(out + ((size_t)(b * F_) + r0 + grp + 8) * (H_ * A_) + c) = o;
        }
    }
}

extern "C" void kernel_launch(void* const* d_in, const int* in_sizes, int n_in,
                              void* d_out, int out_size) {
    const float* feature = (const float*)d_in[0];
    const float* Qw      = (const float*)d_in[1];
    const float* Kw      = (const float*)d_in[2];
    const float* Vw      = (const float*)d_in[3];
    const float* res_w   = (const float*)d_in[4];
    float* out = (float*)d_out;

    cudaFuncSetAttribute(attn_mma_kernel,
                         cudaFuncAttributeMaxDynamicSharedMemorySize, SMEM_BYTES);
    attn_mma_kernel<<<B_ * H_, 256, SMEM_BYTES>>>(feature, Qw, Kw, Vw, res_w, out);
}